// round 1
// baseline (speedup 1.0000x reference)
#include <cuda_runtime.h>
#include <cuda_bf16.h>
#include <math.h>

// Problem constants
#define BATCH   4
#define SEQ     2048
#define DMODEL  1024
#define NHEAD   16
#define DH      64          // DMODEL / NHEAD
#define MTOT    (BATCH * SEQ)       // 8192 rows
#define QKV_N   (3 * DMODEL)        // 3072

// ---------------------------------------------------------------------------
// Scratch (device globals: allocation-free rule)
// ---------------------------------------------------------------------------
__device__ float g_qkv[(size_t)MTOT * QKV_N];   // [8192, 3072]
__device__ float g_att[(size_t)MTOT * DMODEL];  // [8192, 1024] attention output (head-concat)

// ---------------------------------------------------------------------------
// SGEMM with bias: C[M,N] = A[M,K] @ B[K,N] + bias[N]
// 128x128 block, BK=16, 256 threads, 8x8 per-thread microtile, fp32.
// M % 128 == 0, N % 128 == 0, K % 16 == 0 (true for all our shapes).
// ---------------------------------------------------------------------------
#define BM 128
#define BN 128
#define BK 16
#define TM 8
#define TN 8

__global__ __launch_bounds__(256)
void sgemm_bias_kernel(int M, int N, int K,
                       const float* __restrict__ A,
                       const float* __restrict__ B,
                       const float* __restrict__ bias,
                       float* __restrict__ C)
{
    __shared__ float As[BK][BM];     // A transposed tile
    __shared__ float Bs[BK][BN];

    const int bcol = blockIdx.x;     // N tile
    const int brow = blockIdx.y;     // M tile
    const int tid  = threadIdx.x;

    const int tcol = tid % (BN / TN);   // 0..15
    const int trow = tid / (BN / TN);   // 0..15

    // A tile loading indices: BM x BK = 2048 floats = 512 float4; 256 thr -> 2 each
    const int aRow = tid / (BK / 4);          // 0..63
    const int aCol = (tid % (BK / 4)) * 4;    // 0,4,8,12
    // B tile loading: BK x BN = 2048 floats; 256 thr -> 2 each
    const int bRow = tid / (BN / 4);          // 0..7
    const int bCol = (tid % (BN / 4)) * 4;    // 0..124

    const float* Ab = A + (size_t)brow * BM * K;
    const float* Bb = B + (size_t)bcol * BN;

    float acc[TM][TN];
#pragma unroll
    for (int i = 0; i < TM; ++i)
#pragma unroll
        for (int j = 0; j < TN; ++j) acc[i][j] = 0.f;

    float regA[TM], regB[TN];

    for (int k0 = 0; k0 < K; k0 += BK) {
        // Load A tile (transpose into As)
#pragma unroll
        for (int i = 0; i < BM; i += 64) {
            float4 v = *(const float4*)(Ab + (size_t)(aRow + i) * K + k0 + aCol);
            As[aCol + 0][aRow + i] = v.x;
            As[aCol + 1][aRow + i] = v.y;
            As[aCol + 2][aRow + i] = v.z;
            As[aCol + 3][aRow + i] = v.w;
        }
        // Load B tile
#pragma unroll
        for (int i = 0; i < BK; i += 8) {
            *(float4*)(&Bs[bRow + i][bCol]) =
                *(const float4*)(Bb + (size_t)(k0 + bRow + i) * N + bCol);
        }
        __syncthreads();

#pragma unroll
        for (int k = 0; k < BK; ++k) {
#pragma unroll
            for (int i = 0; i < TM; ++i) regA[i] = As[k][trow * TM + i];
#pragma unroll
            for (int j = 0; j < TN; ++j) regB[j] = Bs[k][tcol * TN + j];
#pragma unroll
            for (int i = 0; i < TM; ++i)
#pragma unroll
                for (int j = 0; j < TN; ++j)
                    acc[i][j] += regA[i] * regB[j];
        }
        __syncthreads();
    }

    // Write out with bias
#pragma unroll
    for (int i = 0; i < TM; ++i) {
        const int r = brow * BM + trow * TM + i;
#pragma unroll
        for (int j = 0; j < TN; j += 4) {
            const int c = bcol * BN + tcol * TN + j;
            float4 o;
            o.x = acc[i][j + 0] + bias[c + 0];
            o.y = acc[i][j + 1] + bias[c + 1];
            o.z = acc[i][j + 2] + bias[c + 2];
            o.w = acc[i][j + 3] + bias[c + 3];
            *(float4*)(C + (size_t)r * N + c) = o;
        }
    }
}

// ---------------------------------------------------------------------------
// Causal flash attention, fp32.
// Grid: (SEQ/AT_BM, BATCH*NHEAD). 128 threads; thread t owns query row q0+t.
// Reads q/k/v straight out of the fused qkv buffer [B, T, 3*DMODEL].
// acc[64] register-resident; K/V tiles of 16 rows staged in smem
// (broadcast LDS.128 reads across the warp).
// ---------------------------------------------------------------------------
#define AT_BM 128
#define AT_BN 16
#define QPAD  68          // 64 + 4 pad: conflict-free strided float4 reads

__global__ __launch_bounds__(AT_BM)
void attn_kernel(const float* __restrict__ qkv, float* __restrict__ out)
{
    __shared__ float q_s[AT_BM][QPAD];
    __shared__ float K_s[AT_BN][QPAD];
    __shared__ float V_s[AT_BN][QPAD];

    const int bh = blockIdx.y;
    const int b  = bh / NHEAD;
    const int h  = bh % NHEAD;
    const int q0 = blockIdx.x * AT_BM;
    const int tid = threadIdx.x;
    const int q   = q0 + tid;

    const float* base = qkv + (size_t)b * SEQ * QKV_N;
    const float scale = 0.125f;   // 1/sqrt(64)

    // --- stage Q tile into smem (coalesced) ---
    {
        // 128 rows x 64 floats = 2048 float4; 128 threads -> 16 each
#pragma unroll
        for (int it = 0; it < 16; ++it) {
            const int idx = tid + AT_BM * it;      // 0..2047
            const int n   = idx >> 4;              // row 0..127
            const int d4  = idx & 15;              // float4 col
            float4 v = *(const float4*)(base + (size_t)(q0 + n) * QKV_N + h * DH + d4 * 4);
            *(float4*)&q_s[n][d4 * 4] = v;
        }
    }

    float acc[DH];
#pragma unroll
    for (int d = 0; d < DH; ++d) acc[d] = 0.f;
    float m = -INFINITY;
    float l = 0.f;

    const int kend = q0 + AT_BM;   // exclusive upper bound on key index for this block

    for (int k0 = 0; k0 < kend; k0 += AT_BN) {
        __syncthreads();   // protect K_s/V_s from previous iteration readers
        // --- load K,V tiles: 16 rows x 64 floats = 256 float4 each; 2 per thread each ---
#pragma unroll
        for (int it = 0; it < 2; ++it) {
            const int idx = tid + AT_BM * it;   // 0..255
            const int n   = idx >> 4;
            const int d4  = (idx & 15) * 4;
            const float* krow = base + (size_t)(k0 + n) * QKV_N + DMODEL + h * DH;
            const float* vrow = base + (size_t)(k0 + n) * QKV_N + 2 * DMODEL + h * DH;
            *(float4*)&K_s[n][d4] = *(const float4*)(krow + d4);
            *(float4*)&V_s[n][d4] = *(const float4*)(vrow + d4);
        }
        __syncthreads();

        // --- scores: s[n] = q . k_n ---
        float s[AT_BN];
#pragma unroll
        for (int n = 0; n < AT_BN; ++n) s[n] = 0.f;

#pragma unroll
        for (int dc = 0; dc < DH; dc += 8) {
            float4 qa = *(const float4*)&q_s[tid][dc];
            float4 qb = *(const float4*)&q_s[tid][dc + 4];
#pragma unroll
            for (int n = 0; n < AT_BN; ++n) {
                float4 ka = *(const float4*)&K_s[n][dc];
                float4 kb = *(const float4*)&K_s[n][dc + 4];
                s[n] += qa.x * ka.x + qa.y * ka.y + qa.z * ka.z + qa.w * ka.w
                      + qb.x * kb.x + qb.y * kb.y + qb.z * kb.z + qb.w * kb.w;
            }
        }

        // --- causal mask + online softmax ---
        float mnew = m;
#pragma unroll
        for (int n = 0; n < AT_BN; ++n) {
            s[n] = (k0 + n <= q) ? s[n] * scale : -INFINITY;
            mnew = fmaxf(mnew, s[n]);
        }
        const float corr = __expf(m - mnew);    // 0 when m == -inf
        l *= corr;
#pragma unroll
        for (int d = 0; d < DH; ++d) acc[d] *= corr;
#pragma unroll
        for (int n = 0; n < AT_BN; ++n) {
            s[n] = __expf(s[n] - mnew);         // masked -> exp(-inf)=0
            l += s[n];
        }
        m = mnew;

        // --- PV accumulate ---
#pragma unroll
        for (int n = 0; n < AT_BN; ++n) {
            const float pn = s[n];
            const float4* vrow = (const float4*)&V_s[n][0];
#pragma unroll
            for (int j = 0; j < DH / 4; ++j) {
                float4 v = vrow[j];
                acc[4 * j + 0] += pn * v.x;
                acc[4 * j + 1] += pn * v.y;
                acc[4 * j + 2] += pn * v.z;
                acc[4 * j + 3] += pn * v.w;
            }
        }
    }

    // --- write normalized output: [B*T, DMODEL] head-concat layout ---
    const float rl = 1.0f / l;
    float* orow = out + ((size_t)(b * SEQ + q)) * DMODEL + h * DH;
#pragma unroll
    for (int j = 0; j < DH / 4; ++j) {
        float4 o;
        o.x = acc[4 * j + 0] * rl;
        o.y = acc[4 * j + 1] * rl;
        o.z = acc[4 * j + 2] * rl;
        o.w = acc[4 * j + 3] * rl;
        *((float4*)orow + j) = o;
    }
}

// ---------------------------------------------------------------------------
// kernel_launch
// Inputs (metadata order): x[4,2048,1024] f32, W_qkv[1024,3072] f32,
// b_qkv[3072] f32, W_out[1024,1024] f32, b_out[1024] f32.
// Output: [4,2048,1024] f32.
// ---------------------------------------------------------------------------
extern "C" void kernel_launch(void* const* d_in, const int* in_sizes, int n_in,
                              void* d_out, int out_size)
{
    const float* x     = (const float*)d_in[0];
    const float* W_qkv = (const float*)d_in[1];
    const float* b_qkv = (const float*)d_in[2];
    const float* W_out = (const float*)d_in[3];
    const float* b_out = (const float*)d_in[4];
    float* out = (float*)d_out;

    float* qkv; cudaGetSymbolAddress((void**)&qkv, g_qkv);
    float* att; cudaGetSymbolAddress((void**)&att, g_att);

    // 1) QKV projection: [8192,1024] @ [1024,3072] + b
    {
        dim3 grid(QKV_N / BN, MTOT / BM);   // (24, 64)
        sgemm_bias_kernel<<<grid, 256>>>(MTOT, QKV_N, DMODEL, x, W_qkv, b_qkv, qkv);
    }
    // 2) Causal attention per (b, h)
    {
        dim3 grid(SEQ / AT_BM, BATCH * NHEAD);   // (16, 64)
        attn_kernel<<<grid, AT_BM>>>(qkv, att);
    }
    // 3) Output projection: [8192,1024] @ [1024,1024] + b
    {
        dim3 grid(DMODEL / BN, MTOT / BM);  // (8, 64)
        sgemm_bias_kernel<<<grid, 256>>>(MTOT, DMODEL, DMODEL, att, W_out, b_out, out);
    }
}

// round 3
// speedup vs baseline: 1.4838x; 1.4838x over previous
#include <cuda_runtime.h>
#include <cuda_bf16.h>
#include <math.h>
#include <stdint.h>

// Problem constants
#define BATCH   4
#define SEQ     2048
#define DMODEL  1024
#define NHEAD   16
#define DH      64
#define MTOT    (BATCH * SEQ)       // 8192
#define QKV_N   (3 * DMODEL)        // 3072
#define KDIM    DMODEL              // K of both GEMMs = 1024

// ---------------------------------------------------------------------------
// Scratch (device globals: allocation-free rule)
// ---------------------------------------------------------------------------
__device__ float g_qkv[(size_t)MTOT * QKV_N];      // [8192,3072]
__device__ float g_att[(size_t)MTOT * DMODEL];     // [8192,1024] (tf32-rounded)
__device__ float g_xr[(size_t)MTOT * DMODEL];      // x rounded to tf32
__device__ float g_wt_qkv[(size_t)QKV_N * DMODEL]; // W_qkv^T rounded [3072,1024]
__device__ float g_wt_out[(size_t)DMODEL * DMODEL];// W_out^T rounded [1024,1024]

// ---------------------------------------------------------------------------
// Helpers (all portable PTX: sm_80+ — nothing sm_103a-specific)
// ---------------------------------------------------------------------------
__device__ __forceinline__ uint32_t smem_u32(const void* p) {
    uint32_t a;
    asm("{ .reg .u64 t; cvta.to.shared.u64 t, %1; cvt.u32.u64 %0, t; }" : "=r"(a) : "l"(p));
    return a;
}
__device__ __forceinline__ float round_tf32(float x) {
    uint32_t u;
    asm("cvt.rna.tf32.f32 %0, %1;" : "=r"(u) : "f"(x));
    return __uint_as_float(u);
}
__device__ __forceinline__ void cp16(uint32_t dst, const void* src) {
    asm volatile("cp.async.cg.shared.global [%0], [%1], 16;" :: "r"(dst), "l"(src));
}
#define CP_COMMIT()  asm volatile("cp.async.commit_group;" ::: "memory")
#define CP_WAIT1()   asm volatile("cp.async.wait_group 1;" ::: "memory")
#define CP_WAIT0()   asm volatile("cp.async.wait_group 0;" ::: "memory")

// m16n8k8 tf32 mma, fp32 accumulate (D += A*B)
__device__ __forceinline__ void mma_tf32(float* d, const uint32_t* a, const uint32_t* b) {
    asm volatile(
        "mma.sync.aligned.m16n8k8.row.col.f32.tf32.tf32.f32 "
        "{%0,%1,%2,%3}, {%4,%5,%6,%7}, {%8,%9}, {%0,%1,%2,%3};"
        : "+f"(d[0]), "+f"(d[1]), "+f"(d[2]), "+f"(d[3])
        : "r"(a[0]), "r"(a[1]), "r"(a[2]), "r"(a[3]), "r"(b[0]), "r"(b[1]));
}

// ---------------------------------------------------------------------------
// tf32 mma.sync GEMM: C[M,Ntot] = A[M,1024] @ Bt[Ntot,1024]^T + bias
// CTA tile 128x128, BK=32, 256 threads (8 warps, 2x4), warp tile 64x32.
// Smem row pitch 36 floats (pitch % 32 == 4 -> conflict-free fragment LDS).
// A, Bt must be tf32-prerounded fp32.
// ---------------------------------------------------------------------------
#define GBM 128
#define GBN 128
#define GBK 32
#define PITCH 36
#define TILE_FLOATS (128 * PITCH)              // 4608 floats per tile
#define GEMM_SMEM_BYTES (4 * TILE_FLOATS * 4)  // A0,A1,B0,B1 = 73728 B
#define NCHUNK (KDIM / GBK)                    // 32

__global__ __launch_bounds__(256)
void gemm_tf32_kernel(const float* __restrict__ A, const float* __restrict__ Bt,
                      const float* __restrict__ bias, float* __restrict__ C, int Ntot)
{
    extern __shared__ float sm[];
    float* const sA[2] = { sm,                  sm + TILE_FLOATS };
    float* const sB[2] = { sm + 2 * TILE_FLOATS, sm + 3 * TILE_FLOATS };

    const int tid = threadIdx.x;
    const int wid = tid >> 5;
    const int lane = tid & 31;
    const int g = lane >> 2;        // group id (row within frag)
    const int t = lane & 3;         // thread-in-group (k within frag)
    const int wm = wid >> 2;        // 0..1 : warp m tile (64 rows)
    const int wn = wid & 3;         // 0..3 : warp n tile (32 cols)

    const int m0 = blockIdx.y * GBM;
    const int n0 = blockIdx.x * GBN;

    const float* Abase = A  + (size_t)m0 * KDIM;
    const float* Bbase = Bt + (size_t)n0 * KDIM;

    const uint32_t sAu[2] = { smem_u32(sA[0]), smem_u32(sA[1]) };
    const uint32_t sBu[2] = { smem_u32(sB[0]), smem_u32(sB[1]) };

    // loader: 128 rows x 32 k  ->  1024 16B segs per tile, 256 thr -> 4 each
    auto load_chunk = [&](int c, int st) {
        const int k0 = c * GBK;
#pragma unroll
        for (int i = 0; i < 4; ++i) {
            const int e = tid + 256 * i;           // 0..1023
            const int r = e >> 3, q = e & 7;       // row, 16B-seg
            const uint32_t off = (uint32_t)(r * PITCH + q * 4) * 4u;
            cp16(sAu[st] + off, Abase + (size_t)r * KDIM + k0 + q * 4);
            cp16(sBu[st] + off, Bbase + (size_t)r * KDIM + k0 + q * 4);
        }
        CP_COMMIT();
    };

    float acc[4][4][4];
#pragma unroll
    for (int i = 0; i < 4; ++i)
#pragma unroll
        for (int j = 0; j < 4; ++j)
#pragma unroll
            for (int r = 0; r < 4; ++r) acc[i][j][r] = 0.f;

    load_chunk(0, 0);

    for (int c = 0; c < NCHUNK; ++c) {
        const int s = c & 1;
        if (c + 1 < NCHUNK) {
            load_chunk(c + 1, 1 - s);
            CP_WAIT1();
        } else {
            CP_WAIT0();
        }
        __syncthreads();

        const float* As = sA[s];
        const float* Bs = sB[s];
#pragma unroll
        for (int ks = 0; ks < 4; ++ks) {
            const int koff = ks * 8;
            uint32_t af[4][4], bf[4][2];
#pragma unroll
            for (int mt = 0; mt < 4; ++mt) {
                const int rb = wm * 64 + mt * 16;
                af[mt][0] = __float_as_uint(As[(rb + g)     * PITCH + koff + t]);
                af[mt][1] = __float_as_uint(As[(rb + g + 8) * PITCH + koff + t]);
                af[mt][2] = __float_as_uint(As[(rb + g)     * PITCH + koff + t + 4]);
                af[mt][3] = __float_as_uint(As[(rb + g + 8) * PITCH + koff + t + 4]);
            }
#pragma unroll
            for (int nt = 0; nt < 4; ++nt) {
                const int nb = wn * 32 + nt * 8;
                bf[nt][0] = __float_as_uint(Bs[(nb + g) * PITCH + koff + t]);
                bf[nt][1] = __float_as_uint(Bs[(nb + g) * PITCH + koff + t + 4]);
            }
#pragma unroll
            for (int mt = 0; mt < 4; ++mt)
#pragma unroll
                for (int nt = 0; nt < 4; ++nt)
                    mma_tf32(acc[mt][nt], af[mt], bf[nt]);
        }
        __syncthreads();
    }

    // Epilogue: c0,c1 -> (row, col..col+1); c2,c3 -> (row+8, col..col+1)
#pragma unroll
    for (int mt = 0; mt < 4; ++mt) {
        const int row = m0 + wm * 64 + mt * 16 + g;
#pragma unroll
        for (int nt = 0; nt < 4; ++nt) {
            const int col = n0 + wn * 32 + nt * 8 + t * 2;
            const float bx = __ldg(bias + col), by = __ldg(bias + col + 1);
            float2 lo = { acc[mt][nt][0] + bx, acc[mt][nt][1] + by };
            float2 hi = { acc[mt][nt][2] + bx, acc[mt][nt][3] + by };
            *(float2*)(C + (size_t)row * Ntot + col)       = lo;
            *(float2*)(C + (size_t)(row + 8) * Ntot + col) = hi;
        }
    }
}

// ---------------------------------------------------------------------------
// Transpose + round-to-tf32: Wt[n,k] = rna_tf32(W[k,n]);  W is [K=1024, N]
// ---------------------------------------------------------------------------
__global__ __launch_bounds__(256)
void transpose_round_kernel(const float* __restrict__ W, float* __restrict__ Wt, int N)
{
    __shared__ float tbuf[32][33];
    const int nb = blockIdx.x * 32, kb = blockIdx.y * 32;
    const int tx = threadIdx.x, ty = threadIdx.y;   // 32 x 8
#pragma unroll
    for (int i = 0; i < 32; i += 8)
        tbuf[ty + i][tx] = W[(size_t)(kb + ty + i) * N + nb + tx];
    __syncthreads();
#pragma unroll
    for (int i = 0; i < 32; i += 8)
        Wt[(size_t)(nb + ty + i) * KDIM + kb + tx] = round_tf32(tbuf[tx][ty + i]);
}

__global__ __launch_bounds__(256)
void round_x_kernel(const float* __restrict__ x, float* __restrict__ xr, int n4)
{
    int i = blockIdx.x * blockDim.x + threadIdx.x;
    if (i < n4) {
        float4 v = ((const float4*)x)[i];
        v.x = round_tf32(v.x); v.y = round_tf32(v.y);
        v.z = round_tf32(v.z); v.w = round_tf32(v.w);
        ((float4*)xr)[i] = v;
    }
}

// ---------------------------------------------------------------------------
// Causal flash attention, fp32; output tf32-rounded (feeds tf32 GEMM3).
// ---------------------------------------------------------------------------
#define AT_BM 128
#define AT_BN 16
#define QPAD  68

__global__ __launch_bounds__(AT_BM)
void attn_kernel(const float* __restrict__ qkv, float* __restrict__ out)
{
    __shared__ float q_s[AT_BM][QPAD];
    __shared__ float K_s[AT_BN][QPAD];
    __shared__ float V_s[AT_BN][QPAD];

    const int bh = blockIdx.y;
    const int b  = bh / NHEAD;
    const int h  = bh % NHEAD;
    const int q0 = blockIdx.x * AT_BM;
    const int tid = threadIdx.x;
    const int q   = q0 + tid;

    const float* base = qkv + (size_t)b * SEQ * QKV_N;
    const float scale = 0.125f;

#pragma unroll
    for (int it = 0; it < 16; ++it) {
        const int idx = tid + AT_BM * it;
        const int n   = idx >> 4;
        const int d4  = idx & 15;
        float4 v = *(const float4*)(base + (size_t)(q0 + n) * QKV_N + h * DH + d4 * 4);
        *(float4*)&q_s[n][d4 * 4] = v;
    }

    float acc[DH];
#pragma unroll
    for (int d = 0; d < DH; ++d) acc[d] = 0.f;
    float m = -INFINITY, l = 0.f;

    const int kend = q0 + AT_BM;
    for (int k0 = 0; k0 < kend; k0 += AT_BN) {
        __syncthreads();
#pragma unroll
        for (int it = 0; it < 2; ++it) {
            const int idx = tid + AT_BM * it;
            const int n   = idx >> 4;
            const int d4  = (idx & 15) * 4;
            const float* krow = base + (size_t)(k0 + n) * QKV_N + DMODEL + h * DH;
            const float* vrow = base + (size_t)(k0 + n) * QKV_N + 2 * DMODEL + h * DH;
            *(float4*)&K_s[n][d4] = *(const float4*)(krow + d4);
            *(float4*)&V_s[n][d4] = *(const float4*)(vrow + d4);
        }
        __syncthreads();

        float s[AT_BN];
#pragma unroll
        for (int n = 0; n < AT_BN; ++n) s[n] = 0.f;
#pragma unroll
        for (int dc = 0; dc < DH; dc += 8) {
            float4 qa = *(const float4*)&q_s[tid][dc];
            float4 qb = *(const float4*)&q_s[tid][dc + 4];
#pragma unroll
            for (int n = 0; n < AT_BN; ++n) {
                float4 ka = *(const float4*)&K_s[n][dc];
                float4 kb = *(const float4*)&K_s[n][dc + 4];
                s[n] += qa.x * ka.x + qa.y * ka.y + qa.z * ka.z + qa.w * ka.w
                      + qb.x * kb.x + qb.y * kb.y + qb.z * kb.z + qb.w * kb.w;
            }
        }

        float mnew = m;
#pragma unroll
        for (int n = 0; n < AT_BN; ++n) {
            s[n] = (k0 + n <= q) ? s[n] * scale : -INFINITY;
            mnew = fmaxf(mnew, s[n]);
        }
        const float corr = __expf(m - mnew);
        l *= corr;
#pragma unroll
        for (int d = 0; d < DH; ++d) acc[d] *= corr;
#pragma unroll
        for (int n = 0; n < AT_BN; ++n) { s[n] = __expf(s[n] - mnew); l += s[n]; }
        m = mnew;

#pragma unroll
        for (int n = 0; n < AT_BN; ++n) {
            const float pn = s[n];
            const float4* vrow = (const float4*)&V_s[n][0];
#pragma unroll
            for (int j = 0; j < DH / 4; ++j) {
                float4 v = vrow[j];
                acc[4 * j + 0] += pn * v.x;
                acc[4 * j + 1] += pn * v.y;
                acc[4 * j + 2] += pn * v.z;
                acc[4 * j + 3] += pn * v.w;
            }
        }
    }

    const float rl = 1.0f / l;
    float* orow = out + ((size_t)(b * SEQ + q)) * DMODEL + h * DH;
#pragma unroll
    for (int j = 0; j < DH / 4; ++j) {
        float4 o;
        o.x = round_tf32(acc[4 * j + 0] * rl);
        o.y = round_tf32(acc[4 * j + 1] * rl);
        o.z = round_tf32(acc[4 * j + 2] * rl);
        o.w = round_tf32(acc[4 * j + 3] * rl);
        *((float4*)orow + j) = o;
    }
}

// ---------------------------------------------------------------------------
// kernel_launch
// ---------------------------------------------------------------------------
extern "C" void kernel_launch(void* const* d_in, const int* in_sizes, int n_in,
                              void* d_out, int out_size)
{
    const float* x     = (const float*)d_in[0];
    const float* W_qkv = (const float*)d_in[1];
    const float* b_qkv = (const float*)d_in[2];
    const float* W_out = (const float*)d_in[3];
    const float* b_out = (const float*)d_in[4];
    float* out = (float*)d_out;

    float* qkv;  cudaGetSymbolAddress((void**)&qkv,  g_qkv);
    float* att;  cudaGetSymbolAddress((void**)&att,  g_att);
    float* xr;   cudaGetSymbolAddress((void**)&xr,   g_xr);
    float* wtq;  cudaGetSymbolAddress((void**)&wtq,  g_wt_qkv);
    float* wto;  cudaGetSymbolAddress((void**)&wto,  g_wt_out);

    cudaFuncSetAttribute(gemm_tf32_kernel,
                         cudaFuncAttributeMaxDynamicSharedMemorySize, GEMM_SMEM_BYTES);

    // 0) precondition inputs to tf32 (unbiased RN rounding)
    {
        int n4 = MTOT * DMODEL / 4;
        round_x_kernel<<<(n4 + 255) / 256, 256>>>(x, xr, n4);
        transpose_round_kernel<<<dim3(QKV_N / 32, KDIM / 32), dim3(32, 8)>>>(W_qkv, wtq, QKV_N);
        transpose_round_kernel<<<dim3(DMODEL / 32, KDIM / 32), dim3(32, 8)>>>(W_out, wto, DMODEL);
    }
    // 1) QKV projection (tf32 mma.sync)
    {
        dim3 grid(QKV_N / GBN, MTOT / GBM);   // (24, 64)
        gemm_tf32_kernel<<<grid, 256, GEMM_SMEM_BYTES>>>(xr, wtq, b_qkv, qkv, QKV_N);
    }
    // 2) Causal attention (fp32)
    {
        dim3 grid(SEQ / AT_BM, BATCH * NHEAD);
        attn_kernel<<<grid, AT_BM>>>(qkv, att);
    }
    // 3) Output projection (tf32 mma.sync)
    {
        dim3 grid(DMODEL / GBN, MTOT / GBM);  // (8, 64)
        gemm_tf32_kernel<<<grid, 256, GEMM_SMEM_BYTES>>>(att, wto, b_out, out, DMODEL);
    }
}

// round 4
// speedup vs baseline: 3.4436x; 2.3208x over previous
#include <cuda_runtime.h>
#include <cuda_bf16.h>
#include <math.h>
#include <stdint.h>

// Problem constants
#define BATCH   4
#define SEQ     2048
#define DMODEL  1024
#define NHEAD   16
#define DH      64
#define MTOT    (BATCH * SEQ)       // 8192
#define QKV_N   (3 * DMODEL)        // 3072
#define KDIM    DMODEL

// ---------------------------------------------------------------------------
// Scratch (device globals: allocation-free rule)
// ---------------------------------------------------------------------------
__device__ float g_qkv[(size_t)MTOT * QKV_N];      // [8192,3072] tf32-rounded
__device__ float g_att[(size_t)MTOT * DMODEL];     // [8192,1024] tf32-rounded
__device__ float g_xr[(size_t)MTOT * DMODEL];      // x rounded to tf32
__device__ float g_wt_qkv[(size_t)QKV_N * DMODEL]; // W_qkv^T rounded
__device__ float g_wt_out[(size_t)DMODEL * DMODEL];// W_out^T rounded

// ---------------------------------------------------------------------------
// Helpers (portable sm_80+ PTX only — tcgen05 is rejected by this harness's
// compute_103 ptxas target)
// ---------------------------------------------------------------------------
__device__ __forceinline__ uint32_t smem_u32(const void* p) {
    uint32_t a;
    asm("{ .reg .u64 t; cvta.to.shared.u64 t, %1; cvt.u32.u64 %0, t; }" : "=r"(a) : "l"(p));
    return a;
}
__device__ __forceinline__ float round_tf32(float x) {
    uint32_t u;
    asm("cvt.rna.tf32.f32 %0, %1;" : "=r"(u) : "f"(x));
    return __uint_as_float(u);
}
__device__ __forceinline__ void cp16(uint32_t dst, const void* src) {
    asm volatile("cp.async.cg.shared.global [%0], [%1], 16;" :: "r"(dst), "l"(src));
}
#define CP_COMMIT()  asm volatile("cp.async.commit_group;" ::: "memory")
#define CP_WAIT1()   asm volatile("cp.async.wait_group 1;" ::: "memory")
#define CP_WAIT0()   asm volatile("cp.async.wait_group 0;" ::: "memory")

__device__ __forceinline__ void mma_tf32(float* d, const uint32_t* a, const uint32_t* b) {
    asm volatile(
        "mma.sync.aligned.m16n8k8.row.col.f32.tf32.tf32.f32 "
        "{%0,%1,%2,%3}, {%4,%5,%6,%7}, {%8,%9}, {%0,%1,%2,%3};"
        : "+f"(d[0]), "+f"(d[1]), "+f"(d[2]), "+f"(d[3])
        : "r"(a[0]), "r"(a[1]), "r"(a[2]), "r"(a[3]), "r"(b[0]), "r"(b[1]));
}

// ---------------------------------------------------------------------------
// tf32 mma.sync GEMM: C[M,Ntot] = A[M,1024] @ Bt[Ntot,1024]^T + bias
// (unchanged from round 3 except tf32-rounding flag for the output)
// ---------------------------------------------------------------------------
#define GBM 128
#define GBN 128
#define GBK 32
#define PITCH 36
#define TILE_FLOATS (128 * PITCH)
#define GEMM_SMEM_BYTES (4 * TILE_FLOATS * 4)
#define NCHUNK (KDIM / GBK)

template <int DO_ROUND>
__global__ __launch_bounds__(256)
void gemm_tf32_kernel(const float* __restrict__ A, const float* __restrict__ Bt,
                      const float* __restrict__ bias, float* __restrict__ C, int Ntot)
{
    extern __shared__ float sm[];
    float* const sA[2] = { sm,                   sm + TILE_FLOATS };
    float* const sB[2] = { sm + 2 * TILE_FLOATS, sm + 3 * TILE_FLOATS };

    const int tid = threadIdx.x;
    const int wid = tid >> 5;
    const int lane = tid & 31;
    const int g = lane >> 2;
    const int t = lane & 3;
    const int wm = wid >> 2;
    const int wn = wid & 3;

    const int m0 = blockIdx.y * GBM;
    const int n0 = blockIdx.x * GBN;

    const float* Abase = A  + (size_t)m0 * KDIM;
    const float* Bbase = Bt + (size_t)n0 * KDIM;

    const uint32_t sAu[2] = { smem_u32(sA[0]), smem_u32(sA[1]) };
    const uint32_t sBu[2] = { smem_u32(sB[0]), smem_u32(sB[1]) };

    auto load_chunk = [&](int c, int st) {
        const int k0 = c * GBK;
#pragma unroll
        for (int i = 0; i < 4; ++i) {
            const int e = tid + 256 * i;
            const int r = e >> 3, q = e & 7;
            const uint32_t off = (uint32_t)(r * PITCH + q * 4) * 4u;
            cp16(sAu[st] + off, Abase + (size_t)r * KDIM + k0 + q * 4);
            cp16(sBu[st] + off, Bbase + (size_t)r * KDIM + k0 + q * 4);
        }
        CP_COMMIT();
    };

    float acc[4][4][4];
#pragma unroll
    for (int i = 0; i < 4; ++i)
#pragma unroll
        for (int j = 0; j < 4; ++j)
#pragma unroll
            for (int r = 0; r < 4; ++r) acc[i][j][r] = 0.f;

    load_chunk(0, 0);

    for (int c = 0; c < NCHUNK; ++c) {
        const int s = c & 1;
        if (c + 1 < NCHUNK) { load_chunk(c + 1, 1 - s); CP_WAIT1(); }
        else                { CP_WAIT0(); }
        __syncthreads();

        const float* As = sA[s];
        const float* Bs = sB[s];
#pragma unroll
        for (int ks = 0; ks < 4; ++ks) {
            const int koff = ks * 8;
            uint32_t af[4][4], bf[4][2];
#pragma unroll
            for (int mt = 0; mt < 4; ++mt) {
                const int rb = wm * 64 + mt * 16;
                af[mt][0] = __float_as_uint(As[(rb + g)     * PITCH + koff + t]);
                af[mt][1] = __float_as_uint(As[(rb + g + 8) * PITCH + koff + t]);
                af[mt][2] = __float_as_uint(As[(rb + g)     * PITCH + koff + t + 4]);
                af[mt][3] = __float_as_uint(As[(rb + g + 8) * PITCH + koff + t + 4]);
            }
#pragma unroll
            for (int nt = 0; nt < 4; ++nt) {
                const int nb = wn * 32 + nt * 8;
                bf[nt][0] = __float_as_uint(Bs[(nb + g) * PITCH + koff + t]);
                bf[nt][1] = __float_as_uint(Bs[(nb + g) * PITCH + koff + t + 4]);
            }
#pragma unroll
            for (int mt = 0; mt < 4; ++mt)
#pragma unroll
                for (int nt = 0; nt < 4; ++nt)
                    mma_tf32(acc[mt][nt], af[mt], bf[nt]);
        }
        __syncthreads();
    }

#pragma unroll
    for (int mt = 0; mt < 4; ++mt) {
        const int row = m0 + wm * 64 + mt * 16 + g;
#pragma unroll
        for (int nt = 0; nt < 4; ++nt) {
            const int col = n0 + wn * 32 + nt * 8 + t * 2;
            const float bx = __ldg(bias + col), by = __ldg(bias + col + 1);
            float2 lo, hi;
            if (DO_ROUND) {
                lo = { round_tf32(acc[mt][nt][0] + bx), round_tf32(acc[mt][nt][1] + by) };
                hi = { round_tf32(acc[mt][nt][2] + bx), round_tf32(acc[mt][nt][3] + by) };
            } else {
                lo = { acc[mt][nt][0] + bx, acc[mt][nt][1] + by };
                hi = { acc[mt][nt][2] + bx, acc[mt][nt][3] + by };
            }
            *(float2*)(C + (size_t)row * Ntot + col)       = lo;
            *(float2*)(C + (size_t)(row + 8) * Ntot + col) = hi;
        }
    }
}

// ---------------------------------------------------------------------------
// Preconditioning kernels
// ---------------------------------------------------------------------------
__global__ __launch_bounds__(256)
void transpose_round_kernel(const float* __restrict__ W, float* __restrict__ Wt, int N)
{
    __shared__ float tbuf[32][33];
    const int nb = blockIdx.x * 32, kb = blockIdx.y * 32;
    const int tx = threadIdx.x, ty = threadIdx.y;
#pragma unroll
    for (int i = 0; i < 32; i += 8)
        tbuf[ty + i][tx] = W[(size_t)(kb + ty + i) * N + nb + tx];
    __syncthreads();
#pragma unroll
    for (int i = 0; i < 32; i += 8)
        Wt[(size_t)(nb + ty + i) * KDIM + kb + tx] = round_tf32(tbuf[tx][ty + i]);
}

__global__ __launch_bounds__(256)
void round_x_kernel(const float* __restrict__ x, float* __restrict__ xr, int n4)
{
    int i = blockIdx.x * blockDim.x + threadIdx.x;
    if (i < n4) {
        float4 v = ((const float4*)x)[i];
        v.x = round_tf32(v.x); v.y = round_tf32(v.y);
        v.z = round_tf32(v.z); v.w = round_tf32(v.w);
        ((float4*)xr)[i] = v;
    }
}

// ---------------------------------------------------------------------------
// Tensor-core causal flash attention (tf32 mma.sync).
// CTA: one (b,h) x 128 q rows. 8 warps x 16 rows each (warp-local softmax).
// Iterates 64-key tiles. P routed via warp-private smem (acc->A frag layout).
// Pitches: Q/K/P 68 (banks 4g+t), V 72 (banks 8t+g) — conflict-free frags.
// ---------------------------------------------------------------------------
#define AQP 68
#define AVP 72
// float offsets inside dynamic smem
#define OFF_K  8704      // 128*68
#define OFF_V  13056     // + 64*68
#define OFF_P  17664     // + 64*72
#define ATT_SMEM_FLOATS 26368   // + 128*68
#define ATT_SMEM_BYTES  (ATT_SMEM_FLOATS * 4)

__global__ __launch_bounds__(256)
void attn_mma_kernel(const float* __restrict__ qkv, float* __restrict__ out)
{
    extern __shared__ float sm[];
    const uint32_t smu = smem_u32(sm);

    const int tid = threadIdx.x;
    const int wid = tid >> 5;
    const int lane = tid & 31;
    const int g = lane >> 2, t = lane & 3;

    const int qt = gridDim.x - 1 - blockIdx.x;   // heavy tiles first
    const int q0 = qt * 128;
    const int bh = blockIdx.y;
    const int b = bh >> 4, h = bh & 15;

    const float* base = qkv + (size_t)b * SEQ * QKV_N;

    // --- stage Q (async, once) ---
#pragma unroll
    for (int i = 0; i < 8; ++i) {
        const int e = tid + 256 * i;          // 0..2047
        const int r = e >> 4, seg = e & 15;
        cp16(smu + (uint32_t)(r * AQP + seg * 4) * 4,
             base + (size_t)(q0 + r) * QKV_N + h * DH + seg * 4);
    }
    auto load_kv = [&](int k0) {
#pragma unroll
        for (int i = 0; i < 4; ++i) {
            const int e = tid + 256 * i;      // 0..1023
            const int r = e >> 4, seg = e & 15;
            const float* krow = base + (size_t)(k0 + r) * QKV_N + DMODEL + h * DH + seg * 4;
            const float* vrow = base + (size_t)(k0 + r) * QKV_N + 2 * DMODEL + h * DH + seg * 4;
            cp16(smu + (uint32_t)(OFF_K + r * AQP + seg * 4) * 4, krow);
            cp16(smu + (uint32_t)(OFF_V + r * AVP + seg * 4) * 4, vrow);
        }
    };
    load_kv(0);
    CP_COMMIT(); CP_WAIT0();
    __syncthreads();

    const int niter = 2 * (qt + 1);
    const int row0 = wid * 16 + g;          // smem-local q row (slot 0)
    const int qrow0 = q0 + row0;
    const int qrow1 = qrow0 + 8;
    const float scale = 0.125f;

    float m0 = -INFINITY, m1 = -INFINITY, l0 = 0.f, l1 = 0.f;
    float accO[8][4];
#pragma unroll
    for (int nt = 0; nt < 8; ++nt)
#pragma unroll
        for (int r = 0; r < 4; ++r) accO[nt][r] = 0.f;

    for (int it = 0; it < niter; ++it) {
        const int k0 = it * 64;

        // ---- S = Q K^T  (16 x 64 per warp) ----
        float accS[8][4];
#pragma unroll
        for (int nt = 0; nt < 8; ++nt)
#pragma unroll
            for (int r = 0; r < 4; ++r) accS[nt][r] = 0.f;

#pragma unroll
        for (int kd = 0; kd < 8; ++kd) {
            const int koff = kd * 8;
            uint32_t a[4];
            a[0] = __float_as_uint(sm[(row0)     * AQP + koff + t]);
            a[1] = __float_as_uint(sm[(row0 + 8) * AQP + koff + t]);
            a[2] = __float_as_uint(sm[(row0)     * AQP + koff + t + 4]);
            a[3] = __float_as_uint(sm[(row0 + 8) * AQP + koff + t + 4]);
#pragma unroll
            for (int nt = 0; nt < 8; ++nt) {
                uint32_t bf[2];
                bf[0] = __float_as_uint(sm[OFF_K + (nt * 8 + g) * AQP + koff + t]);
                bf[1] = __float_as_uint(sm[OFF_K + (nt * 8 + g) * AQP + koff + t + 4]);
                mma_tf32(accS[nt], a, bf);
            }
        }

        // ---- scale + causal mask + online softmax (warp-local rows) ----
        float pm0 = -INFINITY, pm1 = -INFINITY;
#pragma unroll
        for (int nt = 0; nt < 8; ++nt) {
            const int key = k0 + nt * 8 + 2 * t;
            accS[nt][0] = (key     <= qrow0) ? accS[nt][0] * scale : -INFINITY;
            accS[nt][1] = (key + 1 <= qrow0) ? accS[nt][1] * scale : -INFINITY;
            accS[nt][2] = (key     <= qrow1) ? accS[nt][2] * scale : -INFINITY;
            accS[nt][3] = (key + 1 <= qrow1) ? accS[nt][3] * scale : -INFINITY;
            pm0 = fmaxf(pm0, fmaxf(accS[nt][0], accS[nt][1]));
            pm1 = fmaxf(pm1, fmaxf(accS[nt][2], accS[nt][3]));
        }
        pm0 = fmaxf(pm0, __shfl_xor_sync(0xffffffffu, pm0, 1));
        pm0 = fmaxf(pm0, __shfl_xor_sync(0xffffffffu, pm0, 2));
        pm1 = fmaxf(pm1, __shfl_xor_sync(0xffffffffu, pm1, 1));
        pm1 = fmaxf(pm1, __shfl_xor_sync(0xffffffffu, pm1, 2));

        const float mn0 = fmaxf(m0, pm0), mn1 = fmaxf(m1, pm1);
        const float c0 = __expf(m0 - mn0), c1 = __expf(m1 - mn1);
        float ls0 = 0.f, ls1 = 0.f;
#pragma unroll
        for (int nt = 0; nt < 8; ++nt) {
            const float p0 = __expf(accS[nt][0] - mn0);
            const float p1 = __expf(accS[nt][1] - mn0);
            const float p2 = __expf(accS[nt][2] - mn1);
            const float p3 = __expf(accS[nt][3] - mn1);
            ls0 += p0 + p1; ls1 += p2 + p3;
            float2 lo = { round_tf32(p0), round_tf32(p1) };
            float2 hi = { round_tf32(p2), round_tf32(p3) };
            *(float2*)&sm[OFF_P + (row0)     * AQP + nt * 8 + 2 * t] = lo;
            *(float2*)&sm[OFF_P + (row0 + 8) * AQP + nt * 8 + 2 * t] = hi;
        }
        ls0 += __shfl_xor_sync(0xffffffffu, ls0, 1);
        ls0 += __shfl_xor_sync(0xffffffffu, ls0, 2);
        ls1 += __shfl_xor_sync(0xffffffffu, ls1, 1);
        ls1 += __shfl_xor_sync(0xffffffffu, ls1, 2);
        l0 = l0 * c0 + ls0;
        l1 = l1 * c1 + ls1;
        m0 = mn0; m1 = mn1;
#pragma unroll
        for (int nt = 0; nt < 8; ++nt) {
            accO[nt][0] *= c0; accO[nt][1] *= c0;
            accO[nt][2] *= c1; accO[nt][3] *= c1;
        }
        __syncwarp();   // P tile is warp-private: warp sync suffices

        // ---- O += P V  (16 x 64 per warp, k = 64 keys) ----
#pragma unroll
        for (int kc = 0; kc < 8; ++kc) {
            uint32_t a[4];
            a[0] = __float_as_uint(sm[OFF_P + (row0)     * AQP + kc * 8 + t]);
            a[1] = __float_as_uint(sm[OFF_P + (row0 + 8) * AQP + kc * 8 + t]);
            a[2] = __float_as_uint(sm[OFF_P + (row0)     * AQP + kc * 8 + t + 4]);
            a[3] = __float_as_uint(sm[OFF_P + (row0 + 8) * AQP + kc * 8 + t + 4]);
#pragma unroll
            for (int nt = 0; nt < 8; ++nt) {
                uint32_t bf[2];
                bf[0] = __float_as_uint(sm[OFF_V + (kc * 8 + t)     * AVP + nt * 8 + g]);
                bf[1] = __float_as_uint(sm[OFF_V + (kc * 8 + t + 4) * AVP + nt * 8 + g]);
                mma_tf32(accO[nt], a, bf);
            }
        }

        // ---- prefetch next K/V ----
        if (it + 1 < niter) {
            __syncthreads();                 // everyone done reading K/V
            load_kv(k0 + 64);
            CP_COMMIT(); CP_WAIT0();
            __syncthreads();
        }
    }

    // ---- normalize + write (tf32-rounded: feeds tf32 out-proj) ----
    const float rl0 = 1.0f / l0, rl1 = 1.0f / l1;
    float* o0 = out + (size_t)(b * SEQ + qrow0) * DMODEL + h * DH;
    float* o1 = out + (size_t)(b * SEQ + qrow1) * DMODEL + h * DH;
#pragma unroll
    for (int nt = 0; nt < 8; ++nt) {
        const int col = nt * 8 + 2 * t;
        float2 lo = { round_tf32(accO[nt][0] * rl0), round_tf32(accO[nt][1] * rl0) };
        float2 hi = { round_tf32(accO[nt][2] * rl1), round_tf32(accO[nt][3] * rl1) };
        *(float2*)(o0 + col) = lo;
        *(float2*)(o1 + col) = hi;
    }
}

// ---------------------------------------------------------------------------
// kernel_launch
// ---------------------------------------------------------------------------
extern "C" void kernel_launch(void* const* d_in, const int* in_sizes, int n_in,
                              void* d_out, int out_size)
{
    const float* x     = (const float*)d_in[0];
    const float* W_qkv = (const float*)d_in[1];
    const float* b_qkv = (const float*)d_in[2];
    const float* W_out = (const float*)d_in[3];
    const float* b_out = (const float*)d_in[4];
    float* out = (float*)d_out;

    float* qkv;  cudaGetSymbolAddress((void**)&qkv,  g_qkv);
    float* att;  cudaGetSymbolAddress((void**)&att,  g_att);
    float* xr;   cudaGetSymbolAddress((void**)&xr,   g_xr);
    float* wtq;  cudaGetSymbolAddress((void**)&wtq,  g_wt_qkv);
    float* wto;  cudaGetSymbolAddress((void**)&wto,  g_wt_out);

    cudaFuncSetAttribute(gemm_tf32_kernel<1>,
                         cudaFuncAttributeMaxDynamicSharedMemorySize, GEMM_SMEM_BYTES);
    cudaFuncSetAttribute(gemm_tf32_kernel<0>,
                         cudaFuncAttributeMaxDynamicSharedMemorySize, GEMM_SMEM_BYTES);
    cudaFuncSetAttribute(attn_mma_kernel,
                         cudaFuncAttributeMaxDynamicSharedMemorySize, ATT_SMEM_BYTES);

    // 0) precondition inputs to tf32
    {
        int n4 = MTOT * DMODEL / 4;
        round_x_kernel<<<(n4 + 255) / 256, 256>>>(x, xr, n4);
        transpose_round_kernel<<<dim3(QKV_N / 32, KDIM / 32), dim3(32, 8)>>>(W_qkv, wtq, QKV_N);
        transpose_round_kernel<<<dim3(DMODEL / 32, KDIM / 32), dim3(32, 8)>>>(W_out, wto, DMODEL);
    }
    // 1) QKV projection (tf32 mma.sync), output rounded to tf32
    {
        dim3 grid(QKV_N / GBN, MTOT / GBM);
        gemm_tf32_kernel<1><<<grid, 256, GEMM_SMEM_BYTES>>>(xr, wtq, b_qkv, qkv, QKV_N);
    }
    // 2) Causal attention (tf32 mma.sync)
    {
        dim3 grid(SEQ / 128, BATCH * NHEAD);   // (16, 64)
        attn_mma_kernel<<<grid, 256, ATT_SMEM_BYTES>>>(qkv, att);
    }
    // 3) Output projection (tf32 mma.sync), full fp32 output
    {
        dim3 grid(DMODEL / GBN, MTOT / GBM);
        gemm_tf32_kernel<0><<<grid, 256, GEMM_SMEM_BYTES>>>(att, wto, b_out, out, DMODEL);
    }
}

// round 5
// speedup vs baseline: 3.8484x; 1.1176x over previous
#include <cuda_runtime.h>
#include <cuda_bf16.h>
#include <math.h>
#include <stdint.h>

// Problem constants
#define BATCH   4
#define SEQ     2048
#define DMODEL  1024
#define NHEAD   16
#define DH      64
#define MTOT    (BATCH * SEQ)       // 8192
#define QKV_N   (3 * DMODEL)        // 3072
#define KDIM    DMODEL

// ---------------------------------------------------------------------------
// Scratch (device globals: allocation-free rule)
// ---------------------------------------------------------------------------
__device__ float g_qkv[(size_t)MTOT * QKV_N];      // [8192,3072] tf32-rounded
__device__ float g_att[(size_t)MTOT * DMODEL];     // [8192,1024] tf32-rounded
__device__ float g_xr[(size_t)MTOT * DMODEL];      // x rounded to tf32
__device__ float g_wt_qkv[(size_t)QKV_N * DMODEL]; // W_qkv^T rounded
__device__ float g_wt_out[(size_t)DMODEL * DMODEL];// W_out^T rounded

// ---------------------------------------------------------------------------
// Helpers (portable sm_80+ PTX only)
// ---------------------------------------------------------------------------
__device__ __forceinline__ uint32_t smem_u32(const void* p) {
    uint32_t a;
    asm("{ .reg .u64 t; cvta.to.shared.u64 t, %1; cvt.u32.u64 %0, t; }" : "=r"(a) : "l"(p));
    return a;
}
__device__ __forceinline__ float round_tf32(float x) {
    uint32_t u;
    asm("cvt.rna.tf32.f32 %0, %1;" : "=r"(u) : "f"(x));
    return __uint_as_float(u);
}
__device__ __forceinline__ void cp16(uint32_t dst, const void* src) {
    asm volatile("cp.async.cg.shared.global [%0], [%1], 16;" :: "r"(dst), "l"(src));
}
#define CP_COMMIT()  asm volatile("cp.async.commit_group;" ::: "memory")
#define CP_WAIT1()   asm volatile("cp.async.wait_group 1;" ::: "memory")
#define CP_WAIT0()   asm volatile("cp.async.wait_group 0;" ::: "memory")

__device__ __forceinline__ void mma_tf32(float* d, const uint32_t* a, const uint32_t* b) {
    asm volatile(
        "mma.sync.aligned.m16n8k8.row.col.f32.tf32.tf32.f32 "
        "{%0,%1,%2,%3}, {%4,%5,%6,%7}, {%8,%9}, {%0,%1,%2,%3};"
        : "+f"(d[0]), "+f"(d[1]), "+f"(d[2]), "+f"(d[3])
        : "r"(a[0]), "r"(a[1]), "r"(a[2]), "r"(a[3]), "r"(b[0]), "r"(b[1]));
}

// ---------------------------------------------------------------------------
// Wide tf32 GEMM: C[M,Ntot] = A[M,1024] @ Bt[Ntot,1024]^T + bias
// CTA tile 128x256, BK=32, 256 threads = 8 warps (2x4), warp tile 64x64.
// 3-stage cp.async pipeline, 1 sync per chunk, 1 CTA/SM.
// Smem pitch 36 floats (pitch % 32 == 4 -> conflict-free fragment LDS).
// ---------------------------------------------------------------------------
#define WBM 128
#define WBN 256
#define WBK 32
#define WP  36
#define WA_FLOATS (WBM * WP)                 // 4608
#define WB_FLOATS (WBN * WP)                 // 9216
#define WSTAGE    (WA_FLOATS + WB_FLOATS)    // 13824 floats
#define WSMEM_BYTES (3 * WSTAGE * 4)         // 165888 B
#define NCHUNK (KDIM / WBK)                  // 32

template <int DO_ROUND>
__global__ __launch_bounds__(256, 1)
void gemm_tf32_wide(const float* __restrict__ A, const float* __restrict__ Bt,
                    const float* __restrict__ bias, float* __restrict__ C, int Ntot)
{
    extern __shared__ float sm[];

    const int tid = threadIdx.x;
    const int wid = tid >> 5;
    const int lane = tid & 31;
    const int g = lane >> 2;      // row in frag
    const int t = lane & 3;       // k/col in frag
    const int wm = wid >> 2;      // 0..1  -> 64 rows
    const int wn = wid & 3;       // 0..3  -> 64 cols

    const int m0 = blockIdx.y * WBM;
    const int n0 = blockIdx.x * WBN;

    const float* Abase = A  + (size_t)m0 * KDIM;
    const float* Bbase = Bt + (size_t)n0 * KDIM;
    const uint32_t smu = smem_u32(sm);

    // loader: A 128x32 (1024 16B segs), B 256x32 (2048 segs) -> 12 per thread
    auto load_chunk = [&](int c, int st) {
        const int k0 = c * WBK;
        const uint32_t sa = smu + (uint32_t)(st * WSTAGE) * 4u;
        const uint32_t sb = sa + (uint32_t)WA_FLOATS * 4u;
#pragma unroll
        for (int i = 0; i < 4; ++i) {
            const int e = tid + 256 * i;            // 0..1023
            const int r = e >> 3, q = e & 7;
            cp16(sa + (uint32_t)(r * WP + q * 4) * 4u, Abase + (size_t)r * KDIM + k0 + q * 4);
        }
#pragma unroll
        for (int i = 0; i < 8; ++i) {
            const int e = tid + 256 * i;            // 0..2047
            const int r = e >> 3, q = e & 7;
            cp16(sb + (uint32_t)(r * WP + q * 4) * 4u, Bbase + (size_t)r * KDIM + k0 + q * 4);
        }
        CP_COMMIT();
    };

    float acc[4][8][4];
#pragma unroll
    for (int i = 0; i < 4; ++i)
#pragma unroll
        for (int j = 0; j < 8; ++j)
#pragma unroll
            for (int r = 0; r < 4; ++r) acc[i][j][r] = 0.f;

    load_chunk(0, 0);
    load_chunk(1, 1);

    for (int c = 0; c < NCHUNK; ++c) {
        const int s = c % 3;
        if (c + 1 < NCHUNK) CP_WAIT1(); else CP_WAIT0();
        __syncthreads();   // chunk c visible to all; stage (c-1)%3 free to overwrite

        const float* As = sm + s * WSTAGE;
        const float* Bs = As + WA_FLOATS;

#pragma unroll
        for (int ks = 0; ks < 4; ++ks) {
            const int koff = ks * 8;
            uint32_t af[4][4];
#pragma unroll
            for (int mt = 0; mt < 4; ++mt) {
                const int rb = wm * 64 + mt * 16;
                af[mt][0] = __float_as_uint(As[(rb + g)     * WP + koff + t]);
                af[mt][1] = __float_as_uint(As[(rb + g + 8) * WP + koff + t]);
                af[mt][2] = __float_as_uint(As[(rb + g)     * WP + koff + t + 4]);
                af[mt][3] = __float_as_uint(As[(rb + g + 8) * WP + koff + t + 4]);
            }
#pragma unroll
            for (int nt = 0; nt < 8; ++nt) {
                const int nb = wn * 64 + nt * 8;
                uint32_t bf[2];
                bf[0] = __float_as_uint(Bs[(nb + g) * WP + koff + t]);
                bf[1] = __float_as_uint(Bs[(nb + g) * WP + koff + t + 4]);
#pragma unroll
                for (int mt = 0; mt < 4; ++mt)
                    mma_tf32(acc[mt][nt], af[mt], bf);
            }
        }

        if (c + 2 < NCHUNK) load_chunk(c + 2, (c + 2) % 3);
    }

    // Epilogue
#pragma unroll
    for (int mt = 0; mt < 4; ++mt) {
        const int row = m0 + wm * 64 + mt * 16 + g;
#pragma unroll
        for (int nt = 0; nt < 8; ++nt) {
            const int col = n0 + wn * 64 + nt * 8 + t * 2;
            const float bx = __ldg(bias + col), by = __ldg(bias + col + 1);
            float2 lo, hi;
            if (DO_ROUND) {
                lo = { round_tf32(acc[mt][nt][0] + bx), round_tf32(acc[mt][nt][1] + by) };
                hi = { round_tf32(acc[mt][nt][2] + bx), round_tf32(acc[mt][nt][3] + by) };
            } else {
                lo = { acc[mt][nt][0] + bx, acc[mt][nt][1] + by };
                hi = { acc[mt][nt][2] + bx, acc[mt][nt][3] + by };
            }
            *(float2*)(C + (size_t)row * Ntot + col)       = lo;
            *(float2*)(C + (size_t)(row + 8) * Ntot + col) = hi;
        }
    }
}

// ---------------------------------------------------------------------------
// Preconditioning kernels
// ---------------------------------------------------------------------------
__global__ __launch_bounds__(256)
void transpose_round_kernel(const float* __restrict__ W, float* __restrict__ Wt, int N)
{
    __shared__ float tbuf[32][33];
    const int nb = blockIdx.x * 32, kb = blockIdx.y * 32;
    const int tx = threadIdx.x, ty = threadIdx.y;
#pragma unroll
    for (int i = 0; i < 32; i += 8)
        tbuf[ty + i][tx] = W[(size_t)(kb + ty + i) * N + nb + tx];
    __syncthreads();
#pragma unroll
    for (int i = 0; i < 32; i += 8)
        Wt[(size_t)(nb + ty + i) * KDIM + kb + tx] = round_tf32(tbuf[tx][ty + i]);
}

__global__ __launch_bounds__(256)
void round_x_kernel(const float* __restrict__ x, float* __restrict__ xr, int n4)
{
    int i = blockIdx.x * blockDim.x + threadIdx.x;
    if (i < n4) {
        float4 v = ((const float4*)x)[i];
        v.x = round_tf32(v.x); v.y = round_tf32(v.y);
        v.z = round_tf32(v.z); v.w = round_tf32(v.w);
        ((float4*)xr)[i] = v;
    }
}

// ---------------------------------------------------------------------------
// Tensor-core causal flash attention (tf32 mma.sync) — unchanged from round 4.
// ---------------------------------------------------------------------------
#define AQP 68
#define AVP 72
#define OFF_K  8704
#define OFF_V  13056
#define OFF_P  17664
#define ATT_SMEM_FLOATS 26368
#define ATT_SMEM_BYTES  (ATT_SMEM_FLOATS * 4)

__global__ __launch_bounds__(256)
void attn_mma_kernel(const float* __restrict__ qkv, float* __restrict__ out)
{
    extern __shared__ float sm[];
    const uint32_t smu = smem_u32(sm);

    const int tid = threadIdx.x;
    const int wid = tid >> 5;
    const int lane = tid & 31;
    const int g = lane >> 2, t = lane & 3;

    const int qt = gridDim.x - 1 - blockIdx.x;
    const int q0 = qt * 128;
    const int bh = blockIdx.y;
    const int b = bh >> 4, h = bh & 15;

    const float* base = qkv + (size_t)b * SEQ * QKV_N;

#pragma unroll
    for (int i = 0; i < 8; ++i) {
        const int e = tid + 256 * i;
        const int r = e >> 4, seg = e & 15;
        cp16(smu + (uint32_t)(r * AQP + seg * 4) * 4,
             base + (size_t)(q0 + r) * QKV_N + h * DH + seg * 4);
    }
    auto load_kv = [&](int k0) {
#pragma unroll
        for (int i = 0; i < 4; ++i) {
            const int e = tid + 256 * i;
            const int r = e >> 4, seg = e & 15;
            const float* krow = base + (size_t)(k0 + r) * QKV_N + DMODEL + h * DH + seg * 4;
            const float* vrow = base + (size_t)(k0 + r) * QKV_N + 2 * DMODEL + h * DH + seg * 4;
            cp16(smu + (uint32_t)(OFF_K + r * AQP + seg * 4) * 4, krow);
            cp16(smu + (uint32_t)(OFF_V + r * AVP + seg * 4) * 4, vrow);
        }
    };
    load_kv(0);
    CP_COMMIT(); CP_WAIT0();
    __syncthreads();

    const int niter = 2 * (qt + 1);
    const int row0 = wid * 16 + g;
    const int qrow0 = q0 + row0;
    const int qrow1 = qrow0 + 8;
    const float scale = 0.125f;

    float m0 = -INFINITY, m1 = -INFINITY, l0 = 0.f, l1 = 0.f;
    float accO[8][4];
#pragma unroll
    for (int nt = 0; nt < 8; ++nt)
#pragma unroll
        for (int r = 0; r < 4; ++r) accO[nt][r] = 0.f;

    for (int it = 0; it < niter; ++it) {
        const int k0 = it * 64;

        float accS[8][4];
#pragma unroll
        for (int nt = 0; nt < 8; ++nt)
#pragma unroll
            for (int r = 0; r < 4; ++r) accS[nt][r] = 0.f;

#pragma unroll
        for (int kd = 0; kd < 8; ++kd) {
            const int koff = kd * 8;
            uint32_t a[4];
            a[0] = __float_as_uint(sm[(row0)     * AQP + koff + t]);
            a[1] = __float_as_uint(sm[(row0 + 8) * AQP + koff + t]);
            a[2] = __float_as_uint(sm[(row0)     * AQP + koff + t + 4]);
            a[3] = __float_as_uint(sm[(row0 + 8) * AQP + koff + t + 4]);
#pragma unroll
            for (int nt = 0; nt < 8; ++nt) {
                uint32_t bf[2];
                bf[0] = __float_as_uint(sm[OFF_K + (nt * 8 + g) * AQP + koff + t]);
                bf[1] = __float_as_uint(sm[OFF_K + (nt * 8 + g) * AQP + koff + t + 4]);
                mma_tf32(accS[nt], a, bf);
            }
        }

        float pm0 = -INFINITY, pm1 = -INFINITY;
#pragma unroll
        for (int nt = 0; nt < 8; ++nt) {
            const int key = k0 + nt * 8 + 2 * t;
            accS[nt][0] = (key     <= qrow0) ? accS[nt][0] * scale : -INFINITY;
            accS[nt][1] = (key + 1 <= qrow0) ? accS[nt][1] * scale : -INFINITY;
            accS[nt][2] = (key     <= qrow1) ? accS[nt][2] * scale : -INFINITY;
            accS[nt][3] = (key + 1 <= qrow1) ? accS[nt][3] * scale : -INFINITY;
            pm0 = fmaxf(pm0, fmaxf(accS[nt][0], accS[nt][1]));
            pm1 = fmaxf(pm1, fmaxf(accS[nt][2], accS[nt][3]));
        }
        pm0 = fmaxf(pm0, __shfl_xor_sync(0xffffffffu, pm0, 1));
        pm0 = fmaxf(pm0, __shfl_xor_sync(0xffffffffu, pm0, 2));
        pm1 = fmaxf(pm1, __shfl_xor_sync(0xffffffffu, pm1, 1));
        pm1 = fmaxf(pm1, __shfl_xor_sync(0xffffffffu, pm1, 2));

        const float mn0 = fmaxf(m0, pm0), mn1 = fmaxf(m1, pm1);
        const float c0 = __expf(m0 - mn0), c1 = __expf(m1 - mn1);
        float ls0 = 0.f, ls1 = 0.f;
#pragma unroll
        for (int nt = 0; nt < 8; ++nt) {
            const float p0 = __expf(accS[nt][0] - mn0);
            const float p1 = __expf(accS[nt][1] - mn0);
            const float p2 = __expf(accS[nt][2] - mn1);
            const float p3 = __expf(accS[nt][3] - mn1);
            ls0 += p0 + p1; ls1 += p2 + p3;
            float2 lo = { round_tf32(p0), round_tf32(p1) };
            float2 hi = { round_tf32(p2), round_tf32(p3) };
            *(float2*)&sm[OFF_P + (row0)     * AQP + nt * 8 + 2 * t] = lo;
            *(float2*)&sm[OFF_P + (row0 + 8) * AQP + nt * 8 + 2 * t] = hi;
        }
        ls0 += __shfl_xor_sync(0xffffffffu, ls0, 1);
        ls0 += __shfl_xor_sync(0xffffffffu, ls0, 2);
        ls1 += __shfl_xor_sync(0xffffffffu, ls1, 1);
        ls1 += __shfl_xor_sync(0xffffffffu, ls1, 2);
        l0 = l0 * c0 + ls0;
        l1 = l1 * c1 + ls1;
        m0 = mn0; m1 = mn1;
#pragma unroll
        for (int nt = 0; nt < 8; ++nt) {
            accO[nt][0] *= c0; accO[nt][1] *= c0;
            accO[nt][2] *= c1; accO[nt][3] *= c1;
        }
        __syncwarp();

#pragma unroll
        for (int kc = 0; kc < 8; ++kc) {
            uint32_t a[4];
            a[0] = __float_as_uint(sm[OFF_P + (row0)     * AQP + kc * 8 + t]);
            a[1] = __float_as_uint(sm[OFF_P + (row0 + 8) * AQP + kc * 8 + t]);
            a[2] = __float_as_uint(sm[OFF_P + (row0)     * AQP + kc * 8 + t + 4]);
            a[3] = __float_as_uint(sm[OFF_P + (row0 + 8) * AQP + kc * 8 + t + 4]);
#pragma unroll
            for (int nt = 0; nt < 8; ++nt) {
                uint32_t bf[2];
                bf[0] = __float_as_uint(sm[OFF_V + (kc * 8 + t)     * AVP + nt * 8 + g]);
                bf[1] = __float_as_uint(sm[OFF_V + (kc * 8 + t + 4) * AVP + nt * 8 + g]);
                mma_tf32(accO[nt], a, bf);
            }
        }

        if (it + 1 < niter) {
            __syncthreads();
            load_kv(k0 + 64);
            CP_COMMIT(); CP_WAIT0();
            __syncthreads();
        }
    }

    const float rl0 = 1.0f / l0, rl1 = 1.0f / l1;
    float* o0 = out + (size_t)(b * SEQ + qrow0) * DMODEL + h * DH;
    float* o1 = out + (size_t)(b * SEQ + qrow1) * DMODEL + h * DH;
#pragma unroll
    for (int nt = 0; nt < 8; ++nt) {
        const int col = nt * 8 + 2 * t;
        float2 lo = { round_tf32(accO[nt][0] * rl0), round_tf32(accO[nt][1] * rl0) };
        float2 hi = { round_tf32(accO[nt][2] * rl1), round_tf32(accO[nt][3] * rl1) };
        *(float2*)(o0 + col) = lo;
        *(float2*)(o1 + col) = hi;
    }
}

// ---------------------------------------------------------------------------
// kernel_launch
// ---------------------------------------------------------------------------
extern "C" void kernel_launch(void* const* d_in, const int* in_sizes, int n_in,
                              void* d_out, int out_size)
{
    const float* x     = (const float*)d_in[0];
    const float* W_qkv = (const float*)d_in[1];
    const float* b_qkv = (const float*)d_in[2];
    const float* W_out = (const float*)d_in[3];
    const float* b_out = (const float*)d_in[4];
    float* out = (float*)d_out;

    float* qkv;  cudaGetSymbolAddress((void**)&qkv,  g_qkv);
    float* att;  cudaGetSymbolAddress((void**)&att,  g_att);
    float* xr;   cudaGetSymbolAddress((void**)&xr,   g_xr);
    float* wtq;  cudaGetSymbolAddress((void**)&wtq,  g_wt_qkv);
    float* wto;  cudaGetSymbolAddress((void**)&wto,  g_wt_out);

    cudaFuncSetAttribute(gemm_tf32_wide<1>,
                         cudaFuncAttributeMaxDynamicSharedMemorySize, WSMEM_BYTES);
    cudaFuncSetAttribute(gemm_tf32_wide<0>,
                         cudaFuncAttributeMaxDynamicSharedMemorySize, WSMEM_BYTES);
    cudaFuncSetAttribute(attn_mma_kernel,
                         cudaFuncAttributeMaxDynamicSharedMemorySize, ATT_SMEM_BYTES);

    // 0) precondition inputs to tf32
    {
        int n4 = MTOT * DMODEL / 4;
        round_x_kernel<<<(n4 + 255) / 256, 256>>>(x, xr, n4);
        transpose_round_kernel<<<dim3(QKV_N / 32, KDIM / 32), dim3(32, 8)>>>(W_qkv, wtq, QKV_N);
        transpose_round_kernel<<<dim3(DMODEL / 32, KDIM / 32), dim3(32, 8)>>>(W_out, wto, DMODEL);
    }
    // 1) QKV projection, output rounded to tf32
    {
        dim3 grid(QKV_N / WBN, MTOT / WBM);   // (12, 64) = 768 CTAs
        gemm_tf32_wide<1><<<grid, 256, WSMEM_BYTES>>>(xr, wtq, b_qkv, qkv, QKV_N);
    }
    // 2) Causal attention (tf32 mma.sync)
    {
        dim3 grid(SEQ / 128, BATCH * NHEAD);  // (16, 64)
        attn_mma_kernel<<<grid, 256, ATT_SMEM_BYTES>>>(qkv, att);
    }
    // 3) Output projection, full fp32 output
    {
        dim3 grid(DMODEL / WBN, MTOT / WBM);  // (4, 64) = 256 CTAs
        gemm_tf32_wide<0><<<grid, 256, WSMEM_BYTES>>>(att, wto, b_out, out, DMODEL);
    }
}